// round 2
// baseline (speedup 1.0000x reference)
#include <cuda_runtime.h>
#include <math.h>

// Problem constants
#define D_MODEL 1024
#define NHEADS  16
#define HDIM    64
#define WINDOW  256
#define BATCH   2
#define SEQ     2048
#define M_TOT   (BATCH * SEQ)   // 4096 rows

// ---------------------------------------------------------------------------
// Scratch (no cudaMalloc allowed): q, k, v, attn-out, each [B*N, D] fp32
// ---------------------------------------------------------------------------
__device__ float g_q[M_TOT * D_MODEL];
__device__ float g_k[M_TOT * D_MODEL];
__device__ float g_v[M_TOT * D_MODEL];
__device__ float g_attn[M_TOT * D_MODEL];

// ---------------------------------------------------------------------------
// SGEMM: C[M,N] = A[M,K] * W[K,N] + bias[N]
// M=4096, N=K=1024. 128x128 block, 8x8 per thread, BK=8, 256 threads.
// ---------------------------------------------------------------------------
#define BM 128
#define BN 128
#define BK 8
#define TM 8
#define TN 8

__global__ __launch_bounds__(256) void sgemm_bias_kernel(
    const float* __restrict__ A, const float* __restrict__ W,
    const float* __restrict__ bias, float* __restrict__ C)
{
    const int K = D_MODEL;
    const int N = D_MODEL;

    __shared__ float As[BK][BM];   // transposed A tile
    __shared__ float Ws[BK][BN];

    const int tid = threadIdx.x;
    const int tx = tid & 15;       // 0..15 -> col group
    const int ty = tid >> 4;       // 0..15 -> row group
    const int m0 = blockIdx.y * BM;
    const int n0 = blockIdx.x * BN;

    // Load mapping
    const int arow = tid >> 1;         // 0..127
    const int acol = (tid & 1) * 4;    // 0 or 4
    const int wrow = tid >> 5;         // 0..7
    const int wcol = (tid & 31) * 4;   // 0..124

    float acc[TM][TN];
#pragma unroll
    for (int i = 0; i < TM; i++)
#pragma unroll
        for (int j = 0; j < TN; j++) acc[i][j] = 0.0f;

    const float* Aptr = A + (size_t)(m0 + arow) * K + acol;
    const float* Wptr = W + (size_t)wrow * N + n0 + wcol;

    for (int kk = 0; kk < K; kk += BK) {
        float4 av = *reinterpret_cast<const float4*>(Aptr + kk);
        As[acol + 0][arow] = av.x;
        As[acol + 1][arow] = av.y;
        As[acol + 2][arow] = av.z;
        As[acol + 3][arow] = av.w;
        float4 wv = *reinterpret_cast<const float4*>(Wptr + (size_t)kk * N);
        *reinterpret_cast<float4*>(&Ws[wrow][wcol]) = wv;
        __syncthreads();

#pragma unroll
        for (int k2 = 0; k2 < BK; k2++) {
            float a[TM], b[TN];
#pragma unroll
            for (int i = 0; i < TM; i += 4) {
                float4 t = *reinterpret_cast<const float4*>(&As[k2][ty * TM + i]);
                a[i + 0] = t.x; a[i + 1] = t.y; a[i + 2] = t.z; a[i + 3] = t.w;
            }
#pragma unroll
            for (int j = 0; j < TN; j += 4) {
                float4 t = *reinterpret_cast<const float4*>(&Ws[k2][tx * TN + j]);
                b[j + 0] = t.x; b[j + 1] = t.y; b[j + 2] = t.z; b[j + 3] = t.w;
            }
#pragma unroll
            for (int i = 0; i < TM; i++)
#pragma unroll
                for (int j = 0; j < TN; j++)
                    acc[i][j] = fmaf(a[i], b[j], acc[i][j]);
        }
        __syncthreads();
    }

    // Epilogue with bias
#pragma unroll
    for (int i = 0; i < TM; i++) {
        int row = m0 + ty * TM + i;
        float* crow = C + (size_t)row * N + n0 + tx * TN;
        const float* brow = bias + n0 + tx * TN;
#pragma unroll
        for (int j = 0; j < TN; j += 4) {
            float4 o;
            o.x = acc[i][j + 0] + brow[j + 0];
            o.y = acc[i][j + 1] + brow[j + 1];
            o.z = acc[i][j + 2] + brow[j + 2];
            o.w = acc[i][j + 3] + brow[j + 3];
            *reinterpret_cast<float4*>(crow + j) = o;
        }
    }
}

// ---------------------------------------------------------------------------
// Windowed causal attention. One thread = one query row. 64 queries/block.
// K/V chunks of 64 keys staged in shared memory.
// Layout: q/k/v are [B*N, D] with head h at column offset h*HDIM.
// ---------------------------------------------------------------------------
#define QB 64
#define KB 64

__global__ __launch_bounds__(QB) void attn_window_kernel(
    const float* __restrict__ q, const float* __restrict__ k,
    const float* __restrict__ v, float* __restrict__ o)
{
    __shared__ float Ks[KB][HDIM];   // stride 64 (== 0 mod 32): conflict-free writes
    __shared__ float Vs[KB][HDIM];

    const int t  = threadIdx.x;              // 0..63
    const int q0 = blockIdx.x * QB;
    const int h  = blockIdx.y;
    const int b  = blockIdx.z;
    const int i  = q0 + t;                   // my query index

    const float scale = 0.125f;              // 1/sqrt(64)

    float qr[HDIM];
    {
        const float* qptr = q + ((size_t)(b * SEQ + i)) * D_MODEL + h * HDIM;
#pragma unroll
        for (int d = 0; d < HDIM; d++) qr[d] = qptr[d] * scale;
    }

    float mmax = -1e30f;
    float lsum = 0.0f;
    float acc[HDIM];
#pragma unroll
    for (int d = 0; d < HDIM; d++) acc[d] = 0.0f;

    const int jlo = i - WINDOW;              // valid keys: [max(0,jlo), i]
    int cstart = q0 - WINDOW;
    if (cstart < 0) cstart = 0;

    for (int c = cstart; c <= q0 + QB - 1; c += KB) {
        // cooperative load of K/V chunk rows c..c+63 (coalesced across threads)
        const float* kbase = k + ((size_t)(b * SEQ + c)) * D_MODEL + h * HDIM;
        const float* vbase = v + ((size_t)(b * SEQ + c)) * D_MODEL + h * HDIM;
        __syncthreads();
#pragma unroll 4
        for (int r = 0; r < KB; r++) {
            Ks[r][t] = kbase[(size_t)r * D_MODEL + t];
            Vs[r][t] = vbase[(size_t)r * D_MODEL + t];
        }
        __syncthreads();

        for (int j = 0; j < KB; j++) {
            const int jj = c + j;
            if (jj > i || jj < jlo) continue;

            float s = 0.0f;
#pragma unroll
            for (int d4 = 0; d4 < HDIM / 4; d4++) {
                float4 kv = *reinterpret_cast<const float4*>(&Ks[j][d4 * 4]);
                s = fmaf(qr[d4 * 4 + 0], kv.x, s);
                s = fmaf(qr[d4 * 4 + 1], kv.y, s);
                s = fmaf(qr[d4 * 4 + 2], kv.z, s);
                s = fmaf(qr[d4 * 4 + 3], kv.w, s);
            }

            if (s > mmax) {                 // rescale only when max moves
                float corr = __expf(mmax - s);
                lsum *= corr;
#pragma unroll
                for (int d = 0; d < HDIM; d++) acc[d] *= corr;
                mmax = s;
            }
            float p = __expf(s - mmax);
            lsum += p;
#pragma unroll
            for (int d4 = 0; d4 < HDIM / 4; d4++) {
                float4 vv = *reinterpret_cast<const float4*>(&Vs[j][d4 * 4]);
                acc[d4 * 4 + 0] = fmaf(p, vv.x, acc[d4 * 4 + 0]);
                acc[d4 * 4 + 1] = fmaf(p, vv.y, acc[d4 * 4 + 1]);
                acc[d4 * 4 + 2] = fmaf(p, vv.z, acc[d4 * 4 + 2]);
                acc[d4 * 4 + 3] = fmaf(p, vv.w, acc[d4 * 4 + 3]);
            }
        }
    }

    const float inv = 1.0f / lsum;
    float* optr = o + ((size_t)(b * SEQ + i)) * D_MODEL + h * HDIM;
#pragma unroll
    for (int d = 0; d < HDIM; d++) optr[d] = acc[d] * inv;
}

// ---------------------------------------------------------------------------
// Launch
// Inputs (metadata order): x, Wq, bq, Wk, bk, Wv, bv, Wo, bo
// ---------------------------------------------------------------------------
extern "C" void kernel_launch(void* const* d_in, const int* in_sizes, int n_in,
                              void* d_out, int out_size)
{
    const float* x  = (const float*)d_in[0];
    const float* Wq = (const float*)d_in[1];
    const float* bq = (const float*)d_in[2];
    const float* Wk = (const float*)d_in[3];
    const float* bk = (const float*)d_in[4];
    const float* Wv = (const float*)d_in[5];
    const float* bv = (const float*)d_in[6];
    const float* Wo = (const float*)d_in[7];
    const float* bo = (const float*)d_in[8];
    float* out = (float*)d_out;

    float *q, *k, *v, *attn;
    cudaGetSymbolAddress((void**)&q,    g_q);
    cudaGetSymbolAddress((void**)&k,    g_k);
    cudaGetSymbolAddress((void**)&v,    g_v);
    cudaGetSymbolAddress((void**)&attn, g_attn);

    dim3 gemm_grid(D_MODEL / BN, M_TOT / BM);   // (8, 32)
    sgemm_bias_kernel<<<gemm_grid, 256>>>(x, Wq, bq, q);
    sgemm_bias_kernel<<<gemm_grid, 256>>>(x, Wk, bk, k);
    sgemm_bias_kernel<<<gemm_grid, 256>>>(x, Wv, bv, v);

    dim3 attn_grid(SEQ / QB, NHEADS, BATCH);    // (32, 16, 2)
    attn_window_kernel<<<attn_grid, QB>>>(q, k, v, attn);

    sgemm_bias_kernel<<<gemm_grid, 256>>>(attn, Wo, bo, out);
}

// round 4
// speedup vs baseline: 1.5685x; 1.5685x over previous
#include <cuda_runtime.h>
#include <cuda_bf16.h>
#include <cstdint>
#include <math.h>

// ---------------------------------------------------------------------------
// Problem constants
// ---------------------------------------------------------------------------
#define D_MODEL 1024
#define NHEADS  16
#define HDIM    64
#define WINDOW  256
#define BATCH   2
#define SEQ     2048
#define M_TOT   (BATCH * SEQ)     // 4096
#define KCAT    3072              // 3 * D_MODEL (hi|hi|lo split GEMM)
#define GCHUNK  64                // bf16 per K chunk (= one 128B SW128 row)
#define NCH     (KCAT / GCHUNK)   // 48

// ---------------------------------------------------------------------------
// Scratch (no cudaMalloc allowed)
// ---------------------------------------------------------------------------
__device__ float g_q[M_TOT * D_MODEL];
__device__ float g_k[M_TOT * D_MODEL];
__device__ float g_v[M_TOT * D_MODEL];
__device__ float g_attn[M_TOT * D_MODEL];
__device__ __nv_bfloat16 g_acat[(size_t)M_TOT * KCAT];          // [4096][3072]
__device__ __nv_bfloat16 g_bcat[4][(size_t)D_MODEL * KCAT];     // [1024 n][3072 k]

// ---------------------------------------------------------------------------
// Helpers
// ---------------------------------------------------------------------------
__device__ __forceinline__ uint32_t smem_u32(const void* p) {
    uint32_t a;
    asm("{ .reg .u64 t; cvta.to.shared.u64 t, %1; cvt.u32.u64 %0, t; }" : "=r"(a) : "l"(p));
    return a;
}
__device__ __forceinline__ uint32_t swz128(uint32_t off) {
    return off ^ ((off >> 3) & 0x70);
}
__device__ __forceinline__ void cp_async16(uint32_t saddr, const void* gaddr) {
    asm volatile("cp.async.cg.shared.global [%0], [%1], 16;" :: "r"(saddr), "l"(gaddr));
}
__device__ __forceinline__ void cp_commit() {
    asm volatile("cp.async.commit_group;" ::: "memory");
}
__device__ __forceinline__ void cp_wait1() {
    asm volatile("cp.async.wait_group 1;" ::: "memory");
}
__device__ __forceinline__ void cp_wait0() {
    asm volatile("cp.async.wait_group 0;" ::: "memory");
}
__device__ __forceinline__ void ldmatrix_x4(uint32_t& r0, uint32_t& r1,
                                            uint32_t& r2, uint32_t& r3, uint32_t addr) {
    asm volatile("ldmatrix.sync.aligned.m8n8.x4.shared.b16 {%0,%1,%2,%3}, [%4];"
                 : "=r"(r0), "=r"(r1), "=r"(r2), "=r"(r3) : "r"(addr));
}
__device__ __forceinline__ void mma16816(float* d, const uint32_t* a,
                                         uint32_t b0, uint32_t b1) {
    asm volatile(
        "mma.sync.aligned.m16n8k16.row.col.f32.bf16.bf16.f32 "
        "{%0,%1,%2,%3}, {%4,%5,%6,%7}, {%8,%9}, {%0,%1,%2,%3};"
        : "+f"(d[0]), "+f"(d[1]), "+f"(d[2]), "+f"(d[3])
        : "r"(a[0]), "r"(a[1]), "r"(a[2]), "r"(a[3]), "r"(b0), "r"(b1));
}

// ---------------------------------------------------------------------------
// convA: src [M,1024] fp32 -> dst [M,3072] bf16 = [hi | hi | lo]
// ---------------------------------------------------------------------------
__global__ __launch_bounds__(256) void convA_kernel(const float* __restrict__ src,
                                                    __nv_bfloat16* __restrict__ dst)
{
    int idx = blockIdx.x * blockDim.x + threadIdx.x;     // over M*1024/4
    float4 v = reinterpret_cast<const float4*>(src)[idx];
    int row = idx >> 8;
    int c4  = idx & 255;

    __nv_bfloat16 hx = __float2bfloat16(v.x), hy = __float2bfloat16(v.y);
    __nv_bfloat16 hz = __float2bfloat16(v.z), hw = __float2bfloat16(v.w);
    __nv_bfloat16 lx = __float2bfloat16(v.x - __bfloat162float(hx));
    __nv_bfloat16 ly = __float2bfloat16(v.y - __bfloat162float(hy));
    __nv_bfloat16 lz = __float2bfloat16(v.z - __bfloat162float(hz));
    __nv_bfloat16 lw = __float2bfloat16(v.w - __bfloat162float(hw));

    __nv_bfloat16* r = dst + (size_t)row * KCAT;
    __nv_bfloat162 h0; h0.x = hx; h0.y = hy;
    __nv_bfloat162 h1; h1.x = hz; h1.y = hw;
    __nv_bfloat162 l0; l0.x = lx; l0.y = ly;
    __nv_bfloat162 l1; l1.x = lz; l1.y = lw;
    __nv_bfloat162* p0 = reinterpret_cast<__nv_bfloat162*>(r) + c4 * 2;
    p0[0] = h0; p0[1] = h1;
    __nv_bfloat162* p1 = reinterpret_cast<__nv_bfloat162*>(r + D_MODEL) + c4 * 2;
    p1[0] = h0; p1[1] = h1;
    __nv_bfloat162* p2 = reinterpret_cast<__nv_bfloat162*>(r + 2 * D_MODEL) + c4 * 2;
    p2[0] = l0; p2[1] = l1;
}

// ---------------------------------------------------------------------------
// convW: W [1024 k][1024 n] fp32 -> B [1024 n][3072 k] bf16 = [hi | lo | hi]
// ---------------------------------------------------------------------------
__global__ __launch_bounds__(256) void convW_kernel(const float* __restrict__ W,
                                                    __nv_bfloat16* __restrict__ B)
{
    __shared__ float tile[32][33];
    int n0 = blockIdx.x * 32;
    int k0 = blockIdx.y * 32;
    int tx = threadIdx.x, ty = threadIdx.y;   // (32, 8)

#pragma unroll
    for (int i = 0; i < 32; i += 8)
        tile[ty + i][tx] = W[(size_t)(k0 + ty + i) * D_MODEL + n0 + tx];
    __syncthreads();

#pragma unroll
    for (int i = 0; i < 32; i += 8) {
        int n = n0 + ty + i;
        int k = k0 + tx;
        float v = tile[tx][ty + i];
        __nv_bfloat16 hi = __float2bfloat16(v);
        __nv_bfloat16 lo = __float2bfloat16(v - __bfloat162float(hi));
        __nv_bfloat16* r = B + (size_t)n * KCAT;
        r[k]               = hi;
        r[D_MODEL + k]     = lo;
        r[2 * D_MODEL + k] = hi;
    }
}

// ---------------------------------------------------------------------------
// Tensor-core GEMM via mma.sync (bf16, fp32 accum):
// C[M,1024] = Acat[M,3072] * Bcat[n][k]^T + bias
// CTA 128x128, BK=64 bf16 (128B SW128 rows), 8 warps (2m x 4n), cp.async x2 buf
// ---------------------------------------------------------------------------
#define GEMM_SMEM_BYTES (64 * 1024 + 1024)

__global__ __launch_bounds__(256) void gemm_mma_kernel(
    const __nv_bfloat16* __restrict__ A,
    const __nv_bfloat16* __restrict__ B,
    const float* __restrict__ bias,
    float* __restrict__ C)
{
    extern __shared__ char dynsmem[];
    uint32_t dyn_base  = smem_u32(dynsmem);
    uint32_t tile_base = (dyn_base + 1023) & ~1023u;
    // layout: A0 @0, B0 @16K, A1 @32K, B1 @48K (each 128 rows x 128B)
    const uint32_t offA[2] = {0u, 32768u};
    const uint32_t offB[2] = {16384u, 49152u};

    const int tid = threadIdx.x;
    const int wid = tid >> 5;
    const int lane = tid & 31;
    const int warp_m = wid >> 2;     // 0..1
    const int warp_n = wid & 3;      // 0..3
    const int m0 = blockIdx.y * 128;
    const int n0 = blockIdx.x * 128;

    // per-thread load mapping: 4 segments for A, 4 for B per chunk
    const int lrow = tid >> 1;               // base row pattern reused per it
    float acc[4][4][4];
#pragma unroll
    for (int i = 0; i < 4; i++)
#pragma unroll
        for (int j = 0; j < 4; j++)
#pragma unroll
            for (int r = 0; r < 4; r++) acc[i][j][r] = 0.0f;
    (void)lrow;

    // ---- chunk loader ----
    auto load_chunk = [&](int ch, int buf) {
        const int kc = ch * GCHUNK;
#pragma unroll
        for (int it = 0; it < 4; it++) {
            int idx = it * 256 + tid;          // 0..1023
            int row = idx >> 3;
            int seg = (idx & 7) << 4;          // byte col 0..112
            uint32_t sw = swz128((uint32_t)(row * 128 + seg));
            cp_async16(tile_base + offA[buf] + sw,
                       reinterpret_cast<const char*>(A + (size_t)(m0 + row) * KCAT + kc) + seg);
            cp_async16(tile_base + offB[buf] + sw,
                       reinterpret_cast<const char*>(B + (size_t)(n0 + row) * KCAT + kc) + seg);
        }
        cp_commit();
    };

    load_chunk(0, 0);

    for (int ch = 0; ch < NCH; ch++) {
        const int buf = ch & 1;
        if (ch + 1 < NCH) {
            load_chunk(ch + 1, buf ^ 1);
            cp_wait1();
        } else {
            cp_wait0();
        }
        __syncthreads();

        const uint32_t baseA = tile_base + offA[buf];
        const uint32_t baseB = tile_base + offB[buf];

#pragma unroll
        for (int step = 0; step < 4; step++) {
            // A fragments: 4 m16 tiles
            uint32_t afr[4][4];
#pragma unroll
            for (int mt = 0; mt < 4; mt++) {
                int row = warp_m * 64 + mt * 16 + (lane & 15);
                int kb  = step * 32 + ((lane >> 4) << 4);
                uint32_t addr = baseA + swz128((uint32_t)(row * 128 + kb));
                ldmatrix_x4(afr[mt][0], afr[mt][1], afr[mt][2], afr[mt][3], addr);
            }
            // B fragments: 4 n8 tiles (two x4 loads, each covers 2 n-tiles)
            uint32_t bfr[8];
#pragma unroll
            for (int jp = 0; jp < 2; jp++) {
                int nrow = warp_n * 32 + jp * 16 + ((lane >> 4) & 1) * 8 + (lane & 7);
                int kb   = step * 32 + ((lane >> 3) & 1) * 16;
                uint32_t addr = baseB + swz128((uint32_t)(nrow * 128 + kb));
                ldmatrix_x4(bfr[jp * 4 + 0], bfr[jp * 4 + 1],
                            bfr[jp * 4 + 2], bfr[jp * 4 + 3], addr);
            }
#pragma unroll
            for (int mt = 0; mt < 4; mt++)
#pragma unroll
                for (int nt = 0; nt < 4; nt++)
                    mma16816(acc[mt][nt], afr[mt], bfr[nt * 2], bfr[nt * 2 + 1]);
        }
        __syncthreads();
    }

    // ---- epilogue: bias + store fp32 ----
#pragma unroll
    for (int mt = 0; mt < 4; mt++) {
        int row = m0 + warp_m * 64 + mt * 16 + (lane >> 2);
#pragma unroll
        for (int nt = 0; nt < 4; nt++) {
            int col = n0 + warp_n * 32 + nt * 8 + (lane & 3) * 2;
            float b0 = bias[col], b1 = bias[col + 1];
            float2 v0; v0.x = acc[mt][nt][0] + b0; v0.y = acc[mt][nt][1] + b1;
            float2 v1; v1.x = acc[mt][nt][2] + b0; v1.y = acc[mt][nt][3] + b1;
            *reinterpret_cast<float2*>(C + (size_t)row * D_MODEL + col) = v0;
            *reinterpret_cast<float2*>(C + (size_t)(row + 8) * D_MODEL + col) = v1;
        }
    }
}

// ---------------------------------------------------------------------------
// Windowed causal attention. One thread = one query row. 128 queries/block.
// ---------------------------------------------------------------------------
#define QB 128
#define KB 64

__global__ __launch_bounds__(QB) void attn_window_kernel(
    const float* __restrict__ q, const float* __restrict__ k,
    const float* __restrict__ v, float* __restrict__ o)
{
    __shared__ float Ks[KB][HDIM];
    __shared__ float Vs[KB][HDIM];

    const int t  = threadIdx.x;              // 0..127
    const int q0 = blockIdx.x * QB;
    const int h  = blockIdx.y;
    const int b  = blockIdx.z;
    const int i  = q0 + t;

    const float scale = 0.125f;              // 1/sqrt(64)

    float qr[HDIM];
    {
        const float* qptr = q + ((size_t)(b * SEQ + i)) * D_MODEL + h * HDIM;
#pragma unroll
        for (int d = 0; d < HDIM; d++) qr[d] = qptr[d] * scale;
    }

    float mmax = -1e30f;
    float lsum = 0.0f;
    float acc[HDIM];
#pragma unroll
    for (int d = 0; d < HDIM; d++) acc[d] = 0.0f;

    const int col = t & 63;
    const int r0  = t >> 6;                  // 0 or 1

    int cstart = q0 - WINDOW;
    if (cstart < 0) cstart = 0;

    for (int c = cstart; c <= q0 + QB - 1; c += KB) {
        const float* kbase = k + ((size_t)(b * SEQ + c)) * D_MODEL + h * HDIM;
        const float* vbase = v + ((size_t)(b * SEQ + c)) * D_MODEL + h * HDIM;
        __syncthreads();
#pragma unroll 4
        for (int r = r0; r < KB; r += 2) {
            Ks[r][col] = kbase[(size_t)r * D_MODEL + col];
            Vs[r][col] = vbase[(size_t)r * D_MODEL + col];
        }
        __syncthreads();

        int jstart = i - WINDOW - c; if (jstart < 0) jstart = 0;
        int jend   = i - c;          if (jend > KB - 1) jend = KB - 1;

        for (int j = jstart; j <= jend; j++) {
            float s = 0.0f;
#pragma unroll
            for (int d4 = 0; d4 < HDIM / 4; d4++) {
                float4 kv = *reinterpret_cast<const float4*>(&Ks[j][d4 * 4]);
                s = fmaf(qr[d4 * 4 + 0], kv.x, s);
                s = fmaf(qr[d4 * 4 + 1], kv.y, s);
                s = fmaf(qr[d4 * 4 + 2], kv.z, s);
                s = fmaf(qr[d4 * 4 + 3], kv.w, s);
            }
            if (s > mmax) {
                float corr = __expf(mmax - s);
                lsum *= corr;
#pragma unroll
                for (int d = 0; d < HDIM; d++) acc[d] *= corr;
                mmax = s;
            }
            float p = __expf(s - mmax);
            lsum += p;
#pragma unroll
            for (int d4 = 0; d4 < HDIM / 4; d4++) {
                float4 vv = *reinterpret_cast<const float4*>(&Vs[j][d4 * 4]);
                acc[d4 * 4 + 0] = fmaf(p, vv.x, acc[d4 * 4 + 0]);
                acc[d4 * 4 + 1] = fmaf(p, vv.y, acc[d4 * 4 + 1]);
                acc[d4 * 4 + 2] = fmaf(p, vv.z, acc[d4 * 4 + 2]);
                acc[d4 * 4 + 3] = fmaf(p, vv.w, acc[d4 * 4 + 3]);
            }
        }
    }

    const float inv = 1.0f / lsum;
    float* optr = o + ((size_t)(b * SEQ + i)) * D_MODEL + h * HDIM;
#pragma unroll
    for (int d = 0; d < HDIM; d++) optr[d] = acc[d] * inv;
}

// ---------------------------------------------------------------------------
// Launch.  Inputs: x, Wq, bq, Wk, bk, Wv, bv, Wo, bo
// ---------------------------------------------------------------------------
extern "C" void kernel_launch(void* const* d_in, const int* in_sizes, int n_in,
                              void* d_out, int out_size)
{
    const float* x  = (const float*)d_in[0];
    const float* Wq = (const float*)d_in[1];
    const float* bq = (const float*)d_in[2];
    const float* Wk = (const float*)d_in[3];
    const float* bk = (const float*)d_in[4];
    const float* Wv = (const float*)d_in[5];
    const float* bv = (const float*)d_in[6];
    const float* Wo = (const float*)d_in[7];
    const float* bo = (const float*)d_in[8];
    float* out = (float*)d_out;

    float *q, *k, *v, *attn;
    __nv_bfloat16 *acat, *bcat;
    cudaGetSymbolAddress((void**)&q,    g_q);
    cudaGetSymbolAddress((void**)&k,    g_k);
    cudaGetSymbolAddress((void**)&v,    g_v);
    cudaGetSymbolAddress((void**)&attn, g_attn);
    cudaGetSymbolAddress((void**)&acat, g_acat);
    cudaGetSymbolAddress((void**)&bcat, g_bcat);

    cudaFuncSetAttribute(gemm_mma_kernel,
                         cudaFuncAttributeMaxDynamicSharedMemorySize, GEMM_SMEM_BYTES);

    const size_t WSTRIDE = (size_t)D_MODEL * KCAT;
    dim3 cw_grid(32, 32), cw_blk(32, 8);
    dim3 gemm_grid(8, 32);                       // (n-tiles, m-tiles)

    convA_kernel<<<M_TOT * D_MODEL / 4 / 256, 256>>>(x, acat);
    convW_kernel<<<cw_grid, cw_blk>>>(Wq, bcat + 0 * WSTRIDE);
    convW_kernel<<<cw_grid, cw_blk>>>(Wk, bcat + 1 * WSTRIDE);
    convW_kernel<<<cw_grid, cw_blk>>>(Wv, bcat + 2 * WSTRIDE);
    convW_kernel<<<cw_grid, cw_blk>>>(Wo, bcat + 3 * WSTRIDE);

    gemm_mma_kernel<<<gemm_grid, 256, GEMM_SMEM_BYTES>>>(acat, bcat + 0 * WSTRIDE, bq, q);
    gemm_mma_kernel<<<gemm_grid, 256, GEMM_SMEM_BYTES>>>(acat, bcat + 1 * WSTRIDE, bk, k);
    gemm_mma_kernel<<<gemm_grid, 256, GEMM_SMEM_BYTES>>>(acat, bcat + 2 * WSTRIDE, bv, v);

    dim3 attn_grid(SEQ / QB, NHEADS, BATCH);     // (16, 16, 2)
    attn_window_kernel<<<attn_grid, QB>>>(q, k, v, attn);

    convA_kernel<<<M_TOT * D_MODEL / 4 / 256, 256>>>(attn, acat);
    gemm_mma_kernel<<<gemm_grid, 256, GEMM_SMEM_BYTES>>>(acat, bcat + 3 * WSTRIDE, bo, out);
}

// round 5
// speedup vs baseline: 3.2651x; 2.0816x over previous
#include <cuda_runtime.h>
#include <cuda_bf16.h>
#include <cstdint>
#include <math.h>

// ---------------------------------------------------------------------------
// Problem constants
// ---------------------------------------------------------------------------
#define D_MODEL 1024
#define NHEADS  16
#define HDIM    64
#define WINDOW  256
#define BATCH   2
#define SEQ     2048
#define M_TOT   (BATCH * SEQ)     // 4096
#define KCAT    3072              // 3 * D_MODEL (hi|hi|lo split GEMM)
#define GCHUNK  64                // bf16 per K chunk (= one 128B SW128 row)
#define NCH     (KCAT / GCHUNK)   // 48

// ---------------------------------------------------------------------------
// Scratch (no cudaMalloc allowed)
// ---------------------------------------------------------------------------
__device__ __nv_bfloat16 g_acat[(size_t)M_TOT * KCAT];          // [4096][3072]
__device__ __nv_bfloat16 g_bcat[4][(size_t)D_MODEL * KCAT];     // [1024 n][3072 k]
__device__ __nv_bfloat16 g_qh[(size_t)M_TOT * D_MODEL];
__device__ __nv_bfloat16 g_ql[(size_t)M_TOT * D_MODEL];
__device__ __nv_bfloat16 g_kh[(size_t)M_TOT * D_MODEL];
__device__ __nv_bfloat16 g_kl[(size_t)M_TOT * D_MODEL];
__device__ __nv_bfloat16 g_vh[(size_t)M_TOT * D_MODEL];
__device__ __nv_bfloat16 g_vl[(size_t)M_TOT * D_MODEL];

// ---------------------------------------------------------------------------
// Helpers
// ---------------------------------------------------------------------------
__device__ __forceinline__ uint32_t smem_u32(const void* p) {
    uint32_t a;
    asm("{ .reg .u64 t; cvta.to.shared.u64 t, %1; cvt.u32.u64 %0, t; }" : "=r"(a) : "l"(p));
    return a;
}
__device__ __forceinline__ uint32_t swz128(uint32_t off) {
    return off ^ ((off >> 3) & 0x70);
}
__device__ __forceinline__ void cp_async16(uint32_t saddr, const void* gaddr) {
    asm volatile("cp.async.cg.shared.global [%0], [%1], 16;" :: "r"(saddr), "l"(gaddr));
}
__device__ __forceinline__ void cp_commit() {
    asm volatile("cp.async.commit_group;" ::: "memory");
}
__device__ __forceinline__ void cp_wait1() {
    asm volatile("cp.async.wait_group 1;" ::: "memory");
}
__device__ __forceinline__ void cp_wait0() {
    asm volatile("cp.async.wait_group 0;" ::: "memory");
}
__device__ __forceinline__ void ldmatrix_x4(uint32_t& r0, uint32_t& r1,
                                            uint32_t& r2, uint32_t& r3, uint32_t addr) {
    asm volatile("ldmatrix.sync.aligned.m8n8.x4.shared.b16 {%0,%1,%2,%3}, [%4];"
                 : "=r"(r0), "=r"(r1), "=r"(r2), "=r"(r3) : "r"(addr));
}
__device__ __forceinline__ void ldmatrix_x4t(uint32_t& r0, uint32_t& r1,
                                             uint32_t& r2, uint32_t& r3, uint32_t addr) {
    asm volatile("ldmatrix.sync.aligned.m8n8.x4.trans.shared.b16 {%0,%1,%2,%3}, [%4];"
                 : "=r"(r0), "=r"(r1), "=r"(r2), "=r"(r3) : "r"(addr));
}
__device__ __forceinline__ void mma16816(float* d, const uint32_t* a,
                                         uint32_t b0, uint32_t b1) {
    asm volatile(
        "mma.sync.aligned.m16n8k16.row.col.f32.bf16.bf16.f32 "
        "{%0,%1,%2,%3}, {%4,%5,%6,%7}, {%8,%9}, {%0,%1,%2,%3};"
        : "+f"(d[0]), "+f"(d[1]), "+f"(d[2]), "+f"(d[3])
        : "r"(a[0]), "r"(a[1]), "r"(a[2]), "r"(a[3]), "r"(b0), "r"(b1));
}
__device__ __forceinline__ uint32_t packbf(float a, float b) {
    uint16_t ua = __bfloat16_as_ushort(__float2bfloat16(a));
    uint16_t ub = __bfloat16_as_ushort(__float2bfloat16(b));
    return (uint32_t)ua | ((uint32_t)ub << 16);
}

// ---------------------------------------------------------------------------
// convA: src [M,1024] fp32 -> dst [M,3072] bf16 = [hi | hi | lo]
// ---------------------------------------------------------------------------
__global__ __launch_bounds__(256) void convA_kernel(const float* __restrict__ src,
                                                    __nv_bfloat16* __restrict__ dst)
{
    int idx = blockIdx.x * blockDim.x + threadIdx.x;
    float4 v = reinterpret_cast<const float4*>(src)[idx];
    int row = idx >> 8;
    int c4  = idx & 255;

    __nv_bfloat16 hx = __float2bfloat16(v.x), hy = __float2bfloat16(v.y);
    __nv_bfloat16 hz = __float2bfloat16(v.z), hw = __float2bfloat16(v.w);
    __nv_bfloat16 lx = __float2bfloat16(v.x - __bfloat162float(hx));
    __nv_bfloat16 ly = __float2bfloat16(v.y - __bfloat162float(hy));
    __nv_bfloat16 lz = __float2bfloat16(v.z - __bfloat162float(hz));
    __nv_bfloat16 lw = __float2bfloat16(v.w - __bfloat162float(hw));

    __nv_bfloat16* r = dst + (size_t)row * KCAT;
    __nv_bfloat162 h0; h0.x = hx; h0.y = hy;
    __nv_bfloat162 h1; h1.x = hz; h1.y = hw;
    __nv_bfloat162 l0; l0.x = lx; l0.y = ly;
    __nv_bfloat162 l1; l1.x = lz; l1.y = lw;
    __nv_bfloat162* p0 = reinterpret_cast<__nv_bfloat162*>(r) + c4 * 2;
    p0[0] = h0; p0[1] = h1;
    __nv_bfloat162* p1 = reinterpret_cast<__nv_bfloat162*>(r + D_MODEL) + c4 * 2;
    p1[0] = h0; p1[1] = h1;
    __nv_bfloat162* p2 = reinterpret_cast<__nv_bfloat162*>(r + 2 * D_MODEL) + c4 * 2;
    p2[0] = l0; p2[1] = l1;
}

// ---------------------------------------------------------------------------
// convW: W [1024 k][1024 n] fp32 -> B [1024 n][3072 k] bf16 = [hi | lo | hi]
// ---------------------------------------------------------------------------
__global__ __launch_bounds__(256) void convW_kernel(const float* __restrict__ W,
                                                    __nv_bfloat16* __restrict__ B)
{
    __shared__ float tile[32][33];
    int n0 = blockIdx.x * 32;
    int k0 = blockIdx.y * 32;
    int tx = threadIdx.x, ty = threadIdx.y;   // (32, 8)

#pragma unroll
    for (int i = 0; i < 32; i += 8)
        tile[ty + i][tx] = W[(size_t)(k0 + ty + i) * D_MODEL + n0 + tx];
    __syncthreads();

#pragma unroll
    for (int i = 0; i < 32; i += 8) {
        int n = n0 + ty + i;
        int k = k0 + tx;
        float v = tile[tx][ty + i];
        __nv_bfloat16 hi = __float2bfloat16(v);
        __nv_bfloat16 lo = __float2bfloat16(v - __bfloat162float(hi));
        __nv_bfloat16* r = B + (size_t)n * KCAT;
        r[k]               = hi;
        r[D_MODEL + k]     = lo;
        r[2 * D_MODEL + k] = hi;
    }
}

// ---------------------------------------------------------------------------
// Tensor-core GEMM: C = Acat[M,3072] * Bcat^T + bias, then either
//   fp32 store (Cf) or split bf16 hi/lo store (Oh/Ol) with scale.
// ---------------------------------------------------------------------------
#define GEMM_SMEM_BYTES (64 * 1024 + 1024)

__global__ __launch_bounds__(256) void gemm_mma_kernel(
    const __nv_bfloat16* __restrict__ A,
    const __nv_bfloat16* __restrict__ B,
    const float* __restrict__ bias,
    float* __restrict__ Cf,
    __nv_bfloat16* __restrict__ Oh,
    __nv_bfloat16* __restrict__ Ol,
    float scale)
{
    extern __shared__ char dynsmem[];
    uint32_t dyn_base  = smem_u32(dynsmem);
    uint32_t tile_base = (dyn_base + 1023) & ~1023u;
    const uint32_t offA[2] = {0u, 32768u};
    const uint32_t offB[2] = {16384u, 49152u};

    const int tid = threadIdx.x;
    const int wid = tid >> 5;
    const int lane = tid & 31;
    const int warp_m = wid >> 2;
    const int warp_n = wid & 3;
    const int m0 = blockIdx.y * 128;
    const int n0 = blockIdx.x * 128;

    float acc[4][4][4];
#pragma unroll
    for (int i = 0; i < 4; i++)
#pragma unroll
        for (int j = 0; j < 4; j++)
#pragma unroll
            for (int r = 0; r < 4; r++) acc[i][j][r] = 0.0f;

    auto load_chunk = [&](int ch, int buf) {
        const int kc = ch * GCHUNK;
#pragma unroll
        for (int it = 0; it < 4; it++) {
            int idx = it * 256 + tid;
            int row = idx >> 3;
            int seg = (idx & 7) << 4;
            uint32_t sw = swz128((uint32_t)(row * 128 + seg));
            cp_async16(tile_base + offA[buf] + sw,
                       reinterpret_cast<const char*>(A + (size_t)(m0 + row) * KCAT + kc) + seg);
            cp_async16(tile_base + offB[buf] + sw,
                       reinterpret_cast<const char*>(B + (size_t)(n0 + row) * KCAT + kc) + seg);
        }
        cp_commit();
    };

    load_chunk(0, 0);

    for (int ch = 0; ch < NCH; ch++) {
        const int buf = ch & 1;
        if (ch + 1 < NCH) {
            load_chunk(ch + 1, buf ^ 1);
            cp_wait1();
        } else {
            cp_wait0();
        }
        __syncthreads();

        const uint32_t baseA = tile_base + offA[buf];
        const uint32_t baseB = tile_base + offB[buf];

#pragma unroll
        for (int step = 0; step < 4; step++) {
            uint32_t afr[4][4];
#pragma unroll
            for (int mt = 0; mt < 4; mt++) {
                int row = warp_m * 64 + mt * 16 + (lane & 15);
                int kb  = step * 32 + ((lane >> 4) << 4);
                uint32_t addr = baseA + swz128((uint32_t)(row * 128 + kb));
                ldmatrix_x4(afr[mt][0], afr[mt][1], afr[mt][2], afr[mt][3], addr);
            }
            uint32_t bfr[8];
#pragma unroll
            for (int jp = 0; jp < 2; jp++) {
                int nrow = warp_n * 32 + jp * 16 + ((lane >> 4) & 1) * 8 + (lane & 7);
                int kb   = step * 32 + ((lane >> 3) & 1) * 16;
                uint32_t addr = baseB + swz128((uint32_t)(nrow * 128 + kb));
                ldmatrix_x4(bfr[jp * 4 + 0], bfr[jp * 4 + 1],
                            bfr[jp * 4 + 2], bfr[jp * 4 + 3], addr);
            }
#pragma unroll
            for (int mt = 0; mt < 4; mt++)
#pragma unroll
                for (int nt = 0; nt < 4; nt++)
                    mma16816(acc[mt][nt], afr[mt], bfr[nt * 2], bfr[nt * 2 + 1]);
        }
        __syncthreads();
    }

    // epilogue
#pragma unroll
    for (int mt = 0; mt < 4; mt++) {
        int row = m0 + warp_m * 64 + mt * 16 + (lane >> 2);
#pragma unroll
        for (int nt = 0; nt < 4; nt++) {
            int col = n0 + warp_n * 32 + nt * 8 + (lane & 3) * 2;
            float b0 = bias[col], b1 = bias[col + 1];
            float v00 = (acc[mt][nt][0] + b0) * scale;
            float v01 = (acc[mt][nt][1] + b1) * scale;
            float v10 = (acc[mt][nt][2] + b0) * scale;
            float v11 = (acc[mt][nt][3] + b1) * scale;
            if (Oh) {
                // split bf16 hi/lo stores
                uint32_t h0 = packbf(v00, v01);
                uint32_t h1 = packbf(v10, v11);
                float r00 = v00 - __bfloat162float(__ushort_as_bfloat16((uint16_t)(h0 & 0xFFFF)));
                float r01 = v01 - __bfloat162float(__ushort_as_bfloat16((uint16_t)(h0 >> 16)));
                float r10 = v10 - __bfloat162float(__ushort_as_bfloat16((uint16_t)(h1 & 0xFFFF)));
                float r11 = v11 - __bfloat162float(__ushort_as_bfloat16((uint16_t)(h1 >> 16)));
                *reinterpret_cast<uint32_t*>(Oh + (size_t)row * D_MODEL + col) = h0;
                *reinterpret_cast<uint32_t*>(Oh + (size_t)(row + 8) * D_MODEL + col) = h1;
                *reinterpret_cast<uint32_t*>(Ol + (size_t)row * D_MODEL + col) = packbf(r00, r01);
                *reinterpret_cast<uint32_t*>(Ol + (size_t)(row + 8) * D_MODEL + col) = packbf(r10, r11);
            } else {
                float2 w0; w0.x = v00; w0.y = v01;
                float2 w1; w1.x = v10; w1.y = v11;
                *reinterpret_cast<float2*>(Cf + (size_t)row * D_MODEL + col) = w0;
                *reinterpret_cast<float2*>(Cf + (size_t)(row + 8) * D_MODEL + col) = w1;
            }
        }
    }
}

// ---------------------------------------------------------------------------
// Tensor-core windowed attention (flash-style, split bf16 precision).
// CTA: 128 q rows x (head, batch). 4 warps x 32 rows. Key chunks of 64.
// Writes output directly into acat [hi | hi | lo] layout.
// ---------------------------------------------------------------------------
#define ATT_SMEM (96 * 1024 + 1024)

__global__ __launch_bounds__(128) void attn_tc_kernel(
    const __nv_bfloat16* __restrict__ qh, const __nv_bfloat16* __restrict__ ql,
    const __nv_bfloat16* __restrict__ kh, const __nv_bfloat16* __restrict__ kl,
    const __nv_bfloat16* __restrict__ vh, const __nv_bfloat16* __restrict__ vl,
    __nv_bfloat16* __restrict__ acat)
{
    extern __shared__ char dynsmem[];
    uint32_t base = (smem_u32(dynsmem) + 1023) & ~1023u;
    const uint32_t QHs = base;
    const uint32_t QLs = base + 16384;
    const uint32_t KV0 = base + 32768;
    const uint32_t KV1 = base + 65536;
    // within KV buffer: Kh@0, Kl@8192, Vh@16384, Vl@24576 (each 64 rows x 128B)

    const int tid = threadIdx.x, wid = tid >> 5, lane = tid & 31;
    const int q0 = blockIdx.x * 128;
    const int h  = blockIdx.y;
    const int b  = blockIdx.z;
    const size_t rowbase = (size_t)b * SEQ + q0;
    const int hoff = h * HDIM;

    // ---- stage Q (hi, lo), 128 rows x 128B, SW128 ----
    {
        const char* qhp = reinterpret_cast<const char*>(qh + rowbase * D_MODEL + hoff);
        const char* qlp = reinterpret_cast<const char*>(ql + rowbase * D_MODEL + hoff);
#pragma unroll
        for (int it = 0; it < 8; it++) {
            int idx = it * 128 + tid;
            int row = idx >> 3;
            int seg = (idx & 7) << 4;
            uint32_t sw = swz128((uint32_t)(row * 128 + seg));
            cp_async16(QHs + sw, qhp + (size_t)row * 2048 + seg);
            cp_async16(QLs + sw, qlp + (size_t)row * 2048 + seg);
        }
        cp_commit();
    }

    int c0 = q0 - WINDOW; if (c0 < 0) c0 = 0;
    const int nch = (q0 + 128 - c0) >> 6;

    auto load_kv = [&](int c, uint32_t kvb) {
        const char* sp0 = reinterpret_cast<const char*>(kh + ((size_t)b * SEQ + c) * D_MODEL + hoff);
        const char* sp1 = reinterpret_cast<const char*>(kl + ((size_t)b * SEQ + c) * D_MODEL + hoff);
        const char* sp2 = reinterpret_cast<const char*>(vh + ((size_t)b * SEQ + c) * D_MODEL + hoff);
        const char* sp3 = reinterpret_cast<const char*>(vl + ((size_t)b * SEQ + c) * D_MODEL + hoff);
#pragma unroll
        for (int it = 0; it < 4; it++) {
            int idx = it * 128 + tid;
            int row = idx >> 3;
            int seg = (idx & 7) << 4;
            uint32_t sw = swz128((uint32_t)(row * 128 + seg));
            size_t go = (size_t)row * 2048 + seg;
            cp_async16(kvb + 0     + sw, sp0 + go);
            cp_async16(kvb + 8192  + sw, sp1 + go);
            cp_async16(kvb + 16384 + sw, sp2 + go);
            cp_async16(kvb + 24576 + sw, sp3 + go);
        }
        cp_commit();
    };

    load_kv(c0, KV0);

    float O[2][8][4];
#pragma unroll
    for (int mt = 0; mt < 2; mt++)
#pragma unroll
        for (int nt = 0; nt < 8; nt++)
#pragma unroll
            for (int r = 0; r < 4; r++) O[mt][nt][r] = 0.0f;
    float mrow[2][2] = {{-1e30f, -1e30f}, {-1e30f, -1e30f}};
    float lrow[2][2] = {{0.f, 0.f}, {0.f, 0.f}};

    const float NEGINF = __int_as_float(0xff800000);

    for (int ch = 0; ch < nch; ch++) {
        const uint32_t kvb = (ch & 1) ? KV1 : KV0;
        if (ch + 1 < nch) {
            load_kv(c0 + (ch + 1) * 64, (ch & 1) ? KV0 : KV1);
            cp_wait1();
        } else {
            cp_wait0();
        }
        __syncthreads();

        const int c = c0 + ch * 64;

        // ---- S = (Q*scale) K^T, split precision ----
        float S[2][8][4];
#pragma unroll
        for (int mt = 0; mt < 2; mt++)
#pragma unroll
            for (int nt = 0; nt < 8; nt++)
#pragma unroll
                for (int r = 0; r < 4; r++) S[mt][nt][r] = 0.0f;

#pragma unroll
        for (int kt = 0; kt < 4; kt++) {
            uint32_t qa[2][4], qla[2][4];
#pragma unroll
            for (int mt = 0; mt < 2; mt++) {
                int row = wid * 32 + mt * 16 + (lane & 15);
                int kb  = kt * 32 + ((lane >> 4) << 4);
                uint32_t sw = swz128((uint32_t)(row * 128 + kb));
                ldmatrix_x4(qa[mt][0], qa[mt][1], qa[mt][2], qa[mt][3], QHs + sw);
                ldmatrix_x4(qla[mt][0], qla[mt][1], qla[mt][2], qla[mt][3], QLs + sw);
            }
#pragma unroll
            for (int np = 0; np < 4; np++) {
                int nr = np * 16 + ((lane >> 4) & 1) * 8 + (lane & 7);
                int kb = kt * 32 + ((lane >> 3) & 1) * 16;
                uint32_t sw = swz128((uint32_t)(nr * 128 + kb));
                uint32_t kf[4], klf[4];
                ldmatrix_x4(kf[0], kf[1], kf[2], kf[3], kvb + 0 + sw);
                ldmatrix_x4(klf[0], klf[1], klf[2], klf[3], kvb + 8192 + sw);
#pragma unroll
                for (int mt = 0; mt < 2; mt++)
#pragma unroll
                    for (int half = 0; half < 2; half++) {
                        int nt = np * 2 + half;
                        mma16816(S[mt][nt], qa[mt],  kf[half * 2],  kf[half * 2 + 1]);
                        mma16816(S[mt][nt], qa[mt],  klf[half * 2], klf[half * 2 + 1]);
                        mma16816(S[mt][nt], qla[mt], kf[half * 2],  kf[half * 2 + 1]);
                    }
            }
        }

        // ---- mask + online softmax + P (bf16 hi/lo) ----
        uint32_t Phi[2][4][4], Plo[2][4][4];
#pragma unroll
        for (int mt = 0; mt < 2; mt++) {
            int i0 = q0 + wid * 32 + mt * 16 + (lane >> 2);
            int i1 = i0 + 8;
#pragma unroll
            for (int nt = 0; nt < 8; nt++) {
                int j = c + nt * 8 + (lane & 3) * 2;
                if (j     > i0 || j     < i0 - WINDOW) S[mt][nt][0] = NEGINF;
                if (j + 1 > i0 || j + 1 < i0 - WINDOW) S[mt][nt][1] = NEGINF;
                if (j     > i1 || j     < i1 - WINDOW) S[mt][nt][2] = NEGINF;
                if (j + 1 > i1 || j + 1 < i1 - WINDOW) S[mt][nt][3] = NEGINF;
            }
#pragma unroll
            for (int half = 0; half < 2; half++) {
                float cm = NEGINF;
#pragma unroll
                for (int nt = 0; nt < 8; nt++)
                    cm = fmaxf(cm, fmaxf(S[mt][nt][half * 2], S[mt][nt][half * 2 + 1]));
                cm = fmaxf(cm, __shfl_xor_sync(0xffffffffu, cm, 1));
                cm = fmaxf(cm, __shfl_xor_sync(0xffffffffu, cm, 2));
                float mold = mrow[mt][half];
                float mnew = fmaxf(mold, cm);        // stays finite (init -1e30)
                float corr = __expf(mold - mnew);
                mrow[mt][half] = mnew;
                float psum = 0.0f;
#pragma unroll
                for (int nt = 0; nt < 8; nt++) {
                    float p0 = __expf(S[mt][nt][half * 2]     - mnew);
                    float p1 = __expf(S[mt][nt][half * 2 + 1] - mnew);
                    psum += p0 + p1;
                    O[mt][nt][half * 2]     *= corr;
                    O[mt][nt][half * 2 + 1] *= corr;
                    uint32_t hp = packbf(p0, p1);
                    float r0 = p0 - __bfloat162float(__ushort_as_bfloat16((uint16_t)(hp & 0xFFFF)));
                    float r1 = p1 - __bfloat162float(__ushort_as_bfloat16((uint16_t)(hp >> 16)));
                    int kt = nt >> 1, hh = nt & 1;
                    Phi[mt][kt][hh * 2 + half] = hp;
                    Plo[mt][kt][hh * 2 + half] = packbf(r0, r1);
                }
                psum += __shfl_xor_sync(0xffffffffu, psum, 1);
                psum += __shfl_xor_sync(0xffffffffu, psum, 2);
                lrow[mt][half] = lrow[mt][half] * corr + psum;
            }
        }

        // ---- O += P V (split precision, V via ldmatrix.trans) ----
#pragma unroll
        for (int kt = 0; kt < 4; kt++) {
#pragma unroll
            for (int np = 0; np < 4; np++) {
                int g = lane >> 3;
                int key = kt * 16 + (g & 1) * 8 + (lane & 7);
                int nb  = np * 32 + ((g >> 1) << 4);
                uint32_t sw = swz128((uint32_t)(key * 128 + nb));
                uint32_t vf[4], vlf[4];
                ldmatrix_x4t(vf[0], vf[1], vf[2], vf[3], kvb + 16384 + sw);
                ldmatrix_x4t(vlf[0], vlf[1], vlf[2], vlf[3], kvb + 24576 + sw);
#pragma unroll
                for (int mt = 0; mt < 2; mt++)
#pragma unroll
                    for (int half = 0; half < 2; half++) {
                        int nt = np * 2 + half;
                        mma16816(O[mt][nt], Phi[mt][kt], vf[half * 2],  vf[half * 2 + 1]);
                        mma16816(O[mt][nt], Phi[mt][kt], vlf[half * 2], vlf[half * 2 + 1]);
                        mma16816(O[mt][nt], Plo[mt][kt], vf[half * 2],  vf[half * 2 + 1]);
                    }
            }
        }
        __syncthreads();
    }

    // ---- normalize + write acat [hi | hi | lo] ----
#pragma unroll
    for (int mt = 0; mt < 2; mt++) {
        size_t rA = rowbase + wid * 32 + mt * 16 + (lane >> 2);
        size_t rB = rA + 8;
        float inv0 = 1.0f / lrow[mt][0];
        float inv1 = 1.0f / lrow[mt][1];
#pragma unroll
        for (int nt = 0; nt < 8; nt++) {
            int col = hoff + nt * 8 + (lane & 3) * 2;
            float o00 = O[mt][nt][0] * inv0, o01 = O[mt][nt][1] * inv0;
            float o10 = O[mt][nt][2] * inv1, o11 = O[mt][nt][3] * inv1;
            uint32_t hA = packbf(o00, o01);
            uint32_t hB = packbf(o10, o11);
            float a0 = o00 - __bfloat162float(__ushort_as_bfloat16((uint16_t)(hA & 0xFFFF)));
            float a1 = o01 - __bfloat162float(__ushort_as_bfloat16((uint16_t)(hA >> 16)));
            float b0 = o10 - __bfloat162float(__ushort_as_bfloat16((uint16_t)(hB & 0xFFFF)));
            float b1 = o11 - __bfloat162float(__ushort_as_bfloat16((uint16_t)(hB >> 16)));
            uint32_t lA = packbf(a0, a1);
            uint32_t lB = packbf(b0, b1);
            __nv_bfloat16* pA = acat + rA * KCAT + col;
            __nv_bfloat16* pB = acat + rB * KCAT + col;
            *reinterpret_cast<uint32_t*>(pA) = hA;
            *reinterpret_cast<uint32_t*>(pA + D_MODEL) = hA;
            *reinterpret_cast<uint32_t*>(pA + 2 * D_MODEL) = lA;
            *reinterpret_cast<uint32_t*>(pB) = hB;
            *reinterpret_cast<uint32_t*>(pB + D_MODEL) = hB;
            *reinterpret_cast<uint32_t*>(pB + 2 * D_MODEL) = lB;
        }
    }
}

// ---------------------------------------------------------------------------
// Launch.  Inputs: x, Wq, bq, Wk, bk, Wv, bv, Wo, bo
// ---------------------------------------------------------------------------
extern "C" void kernel_launch(void* const* d_in, const int* in_sizes, int n_in,
                              void* d_out, int out_size)
{
    const float* x  = (const float*)d_in[0];
    const float* Wq = (const float*)d_in[1];
    const float* bq = (const float*)d_in[2];
    const float* Wk = (const float*)d_in[3];
    const float* bk = (const float*)d_in[4];
    const float* Wv = (const float*)d_in[5];
    const float* bv = (const float*)d_in[6];
    const float* Wo = (const float*)d_in[7];
    const float* bo = (const float*)d_in[8];
    float* out = (float*)d_out;

    __nv_bfloat16 *acat, *bcat, *qh, *ql, *kh, *kl, *vh, *vl;
    cudaGetSymbolAddress((void**)&acat, g_acat);
    cudaGetSymbolAddress((void**)&bcat, g_bcat);
    cudaGetSymbolAddress((void**)&qh, g_qh);
    cudaGetSymbolAddress((void**)&ql, g_ql);
    cudaGetSymbolAddress((void**)&kh, g_kh);
    cudaGetSymbolAddress((void**)&kl, g_kl);
    cudaGetSymbolAddress((void**)&vh, g_vh);
    cudaGetSymbolAddress((void**)&vl, g_vl);

    cudaFuncSetAttribute(gemm_mma_kernel,
                         cudaFuncAttributeMaxDynamicSharedMemorySize, GEMM_SMEM_BYTES);
    cudaFuncSetAttribute(attn_tc_kernel,
                         cudaFuncAttributeMaxDynamicSharedMemorySize, ATT_SMEM);

    const size_t WSTRIDE = (size_t)D_MODEL * KCAT;
    dim3 cw_grid(32, 32), cw_blk(32, 8);
    dim3 gemm_grid(8, 32);

    convA_kernel<<<M_TOT * D_MODEL / 4 / 256, 256>>>(x, acat);
    convW_kernel<<<cw_grid, cw_blk>>>(Wq, bcat + 0 * WSTRIDE);
    convW_kernel<<<cw_grid, cw_blk>>>(Wk, bcat + 1 * WSTRIDE);
    convW_kernel<<<cw_grid, cw_blk>>>(Wv, bcat + 2 * WSTRIDE);
    convW_kernel<<<cw_grid, cw_blk>>>(Wo, bcat + 3 * WSTRIDE);

    // QKV projections -> split bf16 (Q pre-scaled by 1/sqrt(hd) = 0.125, exact)
    gemm_mma_kernel<<<gemm_grid, 256, GEMM_SMEM_BYTES>>>(acat, bcat + 0 * WSTRIDE, bq,
                                                         nullptr, qh, ql, 0.125f);
    gemm_mma_kernel<<<gemm_grid, 256, GEMM_SMEM_BYTES>>>(acat, bcat + 1 * WSTRIDE, bk,
                                                         nullptr, kh, kl, 1.0f);
    gemm_mma_kernel<<<gemm_grid, 256, GEMM_SMEM_BYTES>>>(acat, bcat + 2 * WSTRIDE, bv,
                                                         nullptr, vh, vl, 1.0f);

    // tensor-core windowed attention -> writes acat [hi|hi|lo] directly
    dim3 attn_grid(SEQ / 128, NHEADS, BATCH);    // (16, 16, 2)
    attn_tc_kernel<<<attn_grid, 128, ATT_SMEM>>>(qh, ql, kh, kl, vh, vl, acat);

    // output projection -> fp32
    gemm_mma_kernel<<<gemm_grid, 256, GEMM_SMEM_BYTES>>>(acat, bcat + 3 * WSTRIDE, bo,
                                                         out, nullptr, nullptr, 1.0f);
}

// round 6
// speedup vs baseline: 3.6354x; 1.1134x over previous
#include <cuda_runtime.h>
#include <cuda_bf16.h>
#include <cstdint>
#include <math.h>

// ---------------------------------------------------------------------------
// Problem constants
// ---------------------------------------------------------------------------
#define D_MODEL 1024
#define NHEADS  16
#define HDIM    64
#define WINDOW  256
#define BATCH   2
#define SEQ     2048
#define M_TOT   (BATCH * SEQ)     // 4096
#define KCAT    3072              // 3 * D_MODEL (hi|hi|lo split GEMM)
#define GCHUNK  64                // bf16 per K chunk (= one 128B SW128 row)
#define NCH     (KCAT / GCHUNK)   // 48

// ---------------------------------------------------------------------------
// Scratch (no cudaMalloc allowed)
// ---------------------------------------------------------------------------
__device__ __nv_bfloat16 g_acat[(size_t)M_TOT * KCAT];          // [4096][3072]
__device__ __nv_bfloat16 g_bcat[4][(size_t)D_MODEL * KCAT];     // [1024 n][3072 k]
__device__ __nv_bfloat16 g_qh[(size_t)M_TOT * D_MODEL];
__device__ __nv_bfloat16 g_ql[(size_t)M_TOT * D_MODEL];
__device__ __nv_bfloat16 g_kh[(size_t)M_TOT * D_MODEL];
__device__ __nv_bfloat16 g_kl[(size_t)M_TOT * D_MODEL];
__device__ __nv_bfloat16 g_vh[(size_t)M_TOT * D_MODEL];
__device__ __nv_bfloat16 g_vl[(size_t)M_TOT * D_MODEL];

// ---------------------------------------------------------------------------
// Helpers
// ---------------------------------------------------------------------------
__device__ __forceinline__ uint32_t smem_u32(const void* p) {
    uint32_t a;
    asm("{ .reg .u64 t; cvta.to.shared.u64 t, %1; cvt.u32.u64 %0, t; }" : "=r"(a) : "l"(p));
    return a;
}
__device__ __forceinline__ uint32_t swz128(uint32_t off) {
    return off ^ ((off >> 3) & 0x70);
}
__device__ __forceinline__ void cp_async16(uint32_t saddr, const void* gaddr) {
    asm volatile("cp.async.cg.shared.global [%0], [%1], 16;" :: "r"(saddr), "l"(gaddr));
}
__device__ __forceinline__ void cp_commit() {
    asm volatile("cp.async.commit_group;" ::: "memory");
}
__device__ __forceinline__ void cp_wait2() {
    asm volatile("cp.async.wait_group 2;" ::: "memory");
}
__device__ __forceinline__ void cp_wait1() {
    asm volatile("cp.async.wait_group 1;" ::: "memory");
}
__device__ __forceinline__ void cp_wait0() {
    asm volatile("cp.async.wait_group 0;" ::: "memory");
}
__device__ __forceinline__ void ldmatrix_x4(uint32_t& r0, uint32_t& r1,
                                            uint32_t& r2, uint32_t& r3, uint32_t addr) {
    asm volatile("ldmatrix.sync.aligned.m8n8.x4.shared.b16 {%0,%1,%2,%3}, [%4];"
                 : "=r"(r0), "=r"(r1), "=r"(r2), "=r"(r3) : "r"(addr));
}
__device__ __forceinline__ void ldmatrix_x4t(uint32_t& r0, uint32_t& r1,
                                             uint32_t& r2, uint32_t& r3, uint32_t addr) {
    asm volatile("ldmatrix.sync.aligned.m8n8.x4.trans.shared.b16 {%0,%1,%2,%3}, [%4];"
                 : "=r"(r0), "=r"(r1), "=r"(r2), "=r"(r3) : "r"(addr));
}
__device__ __forceinline__ void mma16816(float* d, const uint32_t* a,
                                         uint32_t b0, uint32_t b1) {
    asm volatile(
        "mma.sync.aligned.m16n8k16.row.col.f32.bf16.bf16.f32 "
        "{%0,%1,%2,%3}, {%4,%5,%6,%7}, {%8,%9}, {%0,%1,%2,%3};"
        : "+f"(d[0]), "+f"(d[1]), "+f"(d[2]), "+f"(d[3])
        : "r"(a[0]), "r"(a[1]), "r"(a[2]), "r"(a[3]), "r"(b0), "r"(b1));
}
__device__ __forceinline__ uint32_t packbf(float a, float b) {
    uint16_t ua = __bfloat16_as_ushort(__float2bfloat16(a));
    uint16_t ub = __bfloat16_as_ushort(__float2bfloat16(b));
    return (uint32_t)ua | ((uint32_t)ub << 16);
}

// ---------------------------------------------------------------------------
// convA: src [M,1024] fp32 -> dst [M,3072] bf16 = [hi | hi | lo]
// ---------------------------------------------------------------------------
__global__ __launch_bounds__(256) void convA_kernel(const float* __restrict__ src,
                                                    __nv_bfloat16* __restrict__ dst)
{
    int idx = blockIdx.x * blockDim.x + threadIdx.x;
    float4 v = reinterpret_cast<const float4*>(src)[idx];
    int row = idx >> 8;
    int c4  = idx & 255;

    __nv_bfloat16 hx = __float2bfloat16(v.x), hy = __float2bfloat16(v.y);
    __nv_bfloat16 hz = __float2bfloat16(v.z), hw = __float2bfloat16(v.w);
    __nv_bfloat16 lx = __float2bfloat16(v.x - __bfloat162float(hx));
    __nv_bfloat16 ly = __float2bfloat16(v.y - __bfloat162float(hy));
    __nv_bfloat16 lz = __float2bfloat16(v.z - __bfloat162float(hz));
    __nv_bfloat16 lw = __float2bfloat16(v.w - __bfloat162float(hw));

    __nv_bfloat16* r = dst + (size_t)row * KCAT;
    __nv_bfloat162 h0; h0.x = hx; h0.y = hy;
    __nv_bfloat162 h1; h1.x = hz; h1.y = hw;
    __nv_bfloat162 l0; l0.x = lx; l0.y = ly;
    __nv_bfloat162 l1; l1.x = lz; l1.y = lw;
    __nv_bfloat162* p0 = reinterpret_cast<__nv_bfloat162*>(r) + c4 * 2;
    p0[0] = h0; p0[1] = h1;
    __nv_bfloat162* p1 = reinterpret_cast<__nv_bfloat162*>(r + D_MODEL) + c4 * 2;
    p1[0] = h0; p1[1] = h1;
    __nv_bfloat162* p2 = reinterpret_cast<__nv_bfloat162*>(r + 2 * D_MODEL) + c4 * 2;
    p2[0] = l0; p2[1] = l1;
}

// ---------------------------------------------------------------------------
// convW (all 4 weights in one launch, blockIdx.z selects the matrix):
// W [1024 k][1024 n] fp32 -> B [1024 n][3072 k] bf16 = [hi | lo | hi]
// ---------------------------------------------------------------------------
__global__ __launch_bounds__(256) void convW4_kernel(
    const float* __restrict__ W0, const float* __restrict__ W1,
    const float* __restrict__ W2, const float* __restrict__ W3,
    __nv_bfloat16* __restrict__ Bbase)
{
    __shared__ float tile[32][33];
    const float* W = (blockIdx.z == 0) ? W0 : (blockIdx.z == 1) ? W1
                     : (blockIdx.z == 2) ? W2 : W3;
    __nv_bfloat16* B = Bbase + (size_t)blockIdx.z * D_MODEL * KCAT;

    int n0 = blockIdx.x * 32;
    int k0 = blockIdx.y * 32;
    int tx = threadIdx.x, ty = threadIdx.y;   // (32, 8)

#pragma unroll
    for (int i = 0; i < 32; i += 8)
        tile[ty + i][tx] = W[(size_t)(k0 + ty + i) * D_MODEL + n0 + tx];
    __syncthreads();

#pragma unroll
    for (int i = 0; i < 32; i += 8) {
        int n = n0 + ty + i;
        int k = k0 + tx;
        float v = tile[tx][ty + i];
        __nv_bfloat16 hi = __float2bfloat16(v);
        __nv_bfloat16 lo = __float2bfloat16(v - __bfloat162float(hi));
        __nv_bfloat16* r = B + (size_t)n * KCAT;
        r[k]               = hi;
        r[D_MODEL + k]     = lo;
        r[2 * D_MODEL + k] = hi;
    }
}

// ---------------------------------------------------------------------------
// GEMM mainloop (3-stage cp.async pipeline), CTA tile 128x128, BK=64 bf16.
// Stages: stage s has A @ s*32768, B @ s*32768+16384.
// ---------------------------------------------------------------------------
#define GEMM_SMEM_BYTES (3 * 32768 + 1024)

__device__ __forceinline__ void gemm_mainloop3(
    const __nv_bfloat16* __restrict__ A, const __nv_bfloat16* __restrict__ B,
    int m0, int n0, uint32_t tile_base, float (&acc)[4][4][4])
{
    const int tid = threadIdx.x;
    const int lane = tid & 31;
    const int wid = tid >> 5;
    const int warp_m = wid >> 2;
    const int warp_n = wid & 3;

#pragma unroll
    for (int i = 0; i < 4; i++)
#pragma unroll
        for (int j = 0; j < 4; j++)
#pragma unroll
            for (int r = 0; r < 4; r++) acc[i][j][r] = 0.0f;

    auto load_chunk = [&](int ch, int s) {
        const int kc = ch * GCHUNK;
        const uint32_t sa = tile_base + s * 32768;
        const uint32_t sb = sa + 16384;
#pragma unroll
        for (int it = 0; it < 4; it++) {
            int idx = it * 256 + tid;
            int row = idx >> 3;
            int seg = (idx & 7) << 4;
            uint32_t sw = swz128((uint32_t)(row * 128 + seg));
            cp_async16(sa + sw,
                       reinterpret_cast<const char*>(A + (size_t)(m0 + row) * KCAT + kc) + seg);
            cp_async16(sb + sw,
                       reinterpret_cast<const char*>(B + (size_t)(n0 + row) * KCAT + kc) + seg);
        }
        cp_commit();
    };

    load_chunk(0, 0);
    load_chunk(1, 1);

    int snext = 2;
    int scur  = 0;
    for (int ch = 0; ch < NCH; ch++) {
        if (ch + 2 < NCH) {
            load_chunk(ch + 2, snext);
            cp_wait2();
        } else if (ch + 1 < NCH) {
            cp_wait1();
        } else {
            cp_wait0();
        }
        __syncthreads();

        const uint32_t baseA = tile_base + scur * 32768;
        const uint32_t baseB = baseA + 16384;

#pragma unroll
        for (int step = 0; step < 4; step++) {
            uint32_t afr[4][4];
#pragma unroll
            for (int mt = 0; mt < 4; mt++) {
                int row = warp_m * 64 + mt * 16 + (lane & 15);
                int kb  = step * 32 + ((lane >> 4) << 4);
                uint32_t addr = baseA + swz128((uint32_t)(row * 128 + kb));
                ldmatrix_x4(afr[mt][0], afr[mt][1], afr[mt][2], afr[mt][3], addr);
            }
            uint32_t bfr[8];
#pragma unroll
            for (int jp = 0; jp < 2; jp++) {
                int nrow = warp_n * 32 + jp * 16 + ((lane >> 4) & 1) * 8 + (lane & 7);
                int kb   = step * 32 + ((lane >> 3) & 1) * 16;
                uint32_t addr = baseB + swz128((uint32_t)(nrow * 128 + kb));
                ldmatrix_x4(bfr[jp * 4 + 0], bfr[jp * 4 + 1],
                            bfr[jp * 4 + 2], bfr[jp * 4 + 3], addr);
            }
#pragma unroll
            for (int mt = 0; mt < 4; mt++)
#pragma unroll
                for (int nt = 0; nt < 4; nt++)
                    mma16816(acc[mt][nt], afr[mt], bfr[nt * 2], bfr[nt * 2 + 1]);
        }
        __syncthreads();

        scur = (scur == 2) ? 0 : scur + 1;
        snext = (snext == 2) ? 0 : snext + 1;
    }
}

// ---------------------------------------------------------------------------
// QKV GEMM: one launch for all three projections.
// blockIdx.x: [0..23] -> matid = x>>3, n-tile = x&7. Split bf16 hi/lo output.
// ---------------------------------------------------------------------------
__global__ __launch_bounds__(256, 2) void qkv_mma_kernel(
    const __nv_bfloat16* __restrict__ A, const __nv_bfloat16* __restrict__ Bc,
    const float* __restrict__ bq, const float* __restrict__ bk, const float* __restrict__ bv,
    __nv_bfloat16* __restrict__ qh, __nv_bfloat16* __restrict__ ql,
    __nv_bfloat16* __restrict__ kh, __nv_bfloat16* __restrict__ kl,
    __nv_bfloat16* __restrict__ vh, __nv_bfloat16* __restrict__ vl)
{
    extern __shared__ char dynsmem[];
    uint32_t tile_base = (smem_u32(dynsmem) + 1023) & ~1023u;

    const int matid = blockIdx.x >> 3;
    const int n0 = (blockIdx.x & 7) * 128;
    const int m0 = blockIdx.y * 128;
    const __nv_bfloat16* B = Bc + (size_t)matid * D_MODEL * KCAT;
    const float* bias = (matid == 0) ? bq : (matid == 1) ? bk : bv;
    __nv_bfloat16* Oh = (matid == 0) ? qh : (matid == 1) ? kh : vh;
    __nv_bfloat16* Ol = (matid == 0) ? ql : (matid == 1) ? kl : vl;
    const float scale = (matid == 0) ? 0.125f : 1.0f;

    float acc[4][4][4];
    gemm_mainloop3(A, B, m0, n0, tile_base, acc);

    const int lane = threadIdx.x & 31;
    const int wid = threadIdx.x >> 5;
    const int warp_m = wid >> 2, warp_n = wid & 3;
#pragma unroll
    for (int mt = 0; mt < 4; mt++) {
        int row = m0 + warp_m * 64 + mt * 16 + (lane >> 2);
#pragma unroll
        for (int nt = 0; nt < 4; nt++) {
            int col = n0 + warp_n * 32 + nt * 8 + (lane & 3) * 2;
            float b0 = bias[col], b1 = bias[col + 1];
            float v00 = (acc[mt][nt][0] + b0) * scale;
            float v01 = (acc[mt][nt][1] + b1) * scale;
            float v10 = (acc[mt][nt][2] + b0) * scale;
            float v11 = (acc[mt][nt][3] + b1) * scale;
            uint32_t h0 = packbf(v00, v01);
            uint32_t h1 = packbf(v10, v11);
            float r00 = v00 - __bfloat162float(__ushort_as_bfloat16((uint16_t)(h0 & 0xFFFF)));
            float r01 = v01 - __bfloat162float(__ushort_as_bfloat16((uint16_t)(h0 >> 16)));
            float r10 = v10 - __bfloat162float(__ushort_as_bfloat16((uint16_t)(h1 & 0xFFFF)));
            float r11 = v11 - __bfloat162float(__ushort_as_bfloat16((uint16_t)(h1 >> 16)));
            *reinterpret_cast<uint32_t*>(Oh + (size_t)row * D_MODEL + col) = h0;
            *reinterpret_cast<uint32_t*>(Oh + (size_t)(row + 8) * D_MODEL + col) = h1;
            *reinterpret_cast<uint32_t*>(Ol + (size_t)row * D_MODEL + col) = packbf(r00, r01);
            *reinterpret_cast<uint32_t*>(Ol + (size_t)(row + 8) * D_MODEL + col) = packbf(r10, r11);
        }
    }
}

// ---------------------------------------------------------------------------
// Output projection GEMM (fp32 epilogue)
// ---------------------------------------------------------------------------
__global__ __launch_bounds__(256, 2) void oproj_mma_kernel(
    const __nv_bfloat16* __restrict__ A, const __nv_bfloat16* __restrict__ B,
    const float* __restrict__ bias, float* __restrict__ C)
{
    extern __shared__ char dynsmem[];
    uint32_t tile_base = (smem_u32(dynsmem) + 1023) & ~1023u;

    const int n0 = blockIdx.x * 128;
    const int m0 = blockIdx.y * 128;

    float acc[4][4][4];
    gemm_mainloop3(A, B, m0, n0, tile_base, acc);

    const int lane = threadIdx.x & 31;
    const int wid = threadIdx.x >> 5;
    const int warp_m = wid >> 2, warp_n = wid & 3;
#pragma unroll
    for (int mt = 0; mt < 4; mt++) {
        int row = m0 + warp_m * 64 + mt * 16 + (lane >> 2);
#pragma unroll
        for (int nt = 0; nt < 4; nt++) {
            int col = n0 + warp_n * 32 + nt * 8 + (lane & 3) * 2;
            float b0 = bias[col], b1 = bias[col + 1];
            float2 w0; w0.x = acc[mt][nt][0] + b0; w0.y = acc[mt][nt][1] + b1;
            float2 w1; w1.x = acc[mt][nt][2] + b0; w1.y = acc[mt][nt][3] + b1;
            *reinterpret_cast<float2*>(C + (size_t)row * D_MODEL + col) = w0;
            *reinterpret_cast<float2*>(C + (size_t)(row + 8) * D_MODEL + col) = w1;
        }
    }
}

// ---------------------------------------------------------------------------
// Tensor-core windowed attention (flash-style, split bf16 precision).
// CTA: 128 q rows x (head, batch). 4 warps x 32 rows. Key chunks of 64.
// Writes output directly into acat [hi | hi | lo] layout.
// ---------------------------------------------------------------------------
#define ATT_SMEM (96 * 1024 + 1024)

__global__ __launch_bounds__(128) void attn_tc_kernel(
    const __nv_bfloat16* __restrict__ qh, const __nv_bfloat16* __restrict__ ql,
    const __nv_bfloat16* __restrict__ kh, const __nv_bfloat16* __restrict__ kl,
    const __nv_bfloat16* __restrict__ vh, const __nv_bfloat16* __restrict__ vl,
    __nv_bfloat16* __restrict__ acat)
{
    extern __shared__ char dynsmem[];
    uint32_t base = (smem_u32(dynsmem) + 1023) & ~1023u;
    const uint32_t QHs = base;
    const uint32_t QLs = base + 16384;
    const uint32_t KV0 = base + 32768;
    const uint32_t KV1 = base + 65536;

    const int tid = threadIdx.x, wid = tid >> 5, lane = tid & 31;
    const int q0 = blockIdx.x * 128;
    const int h  = blockIdx.y;
    const int b  = blockIdx.z;
    const size_t rowbase = (size_t)b * SEQ + q0;
    const int hoff = h * HDIM;

    {
        const char* qhp = reinterpret_cast<const char*>(qh + rowbase * D_MODEL + hoff);
        const char* qlp = reinterpret_cast<const char*>(ql + rowbase * D_MODEL + hoff);
#pragma unroll
        for (int it = 0; it < 8; it++) {
            int idx = it * 128 + tid;
            int row = idx >> 3;
            int seg = (idx & 7) << 4;
            uint32_t sw = swz128((uint32_t)(row * 128 + seg));
            cp_async16(QHs + sw, qhp + (size_t)row * 2048 + seg);
            cp_async16(QLs + sw, qlp + (size_t)row * 2048 + seg);
        }
        cp_commit();
    }

    int c0 = q0 - WINDOW; if (c0 < 0) c0 = 0;
    const int nch = (q0 + 128 - c0) >> 6;

    auto load_kv = [&](int c, uint32_t kvb) {
        const char* sp0 = reinterpret_cast<const char*>(kh + ((size_t)b * SEQ + c) * D_MODEL + hoff);
        const char* sp1 = reinterpret_cast<const char*>(kl + ((size_t)b * SEQ + c) * D_MODEL + hoff);
        const char* sp2 = reinterpret_cast<const char*>(vh + ((size_t)b * SEQ + c) * D_MODEL + hoff);
        const char* sp3 = reinterpret_cast<const char*>(vl + ((size_t)b * SEQ + c) * D_MODEL + hoff);
#pragma unroll
        for (int it = 0; it < 4; it++) {
            int idx = it * 128 + tid;
            int row = idx >> 3;
            int seg = (idx & 7) << 4;
            uint32_t sw = swz128((uint32_t)(row * 128 + seg));
            size_t go = (size_t)row * 2048 + seg;
            cp_async16(kvb + 0     + sw, sp0 + go);
            cp_async16(kvb + 8192  + sw, sp1 + go);
            cp_async16(kvb + 16384 + sw, sp2 + go);
            cp_async16(kvb + 24576 + sw, sp3 + go);
        }
        cp_commit();
    };

    load_kv(c0, KV0);

    float O[2][8][4];
#pragma unroll
    for (int mt = 0; mt < 2; mt++)
#pragma unroll
        for (int nt = 0; nt < 8; nt++)
#pragma unroll
            for (int r = 0; r < 4; r++) O[mt][nt][r] = 0.0f;
    float mrow[2][2] = {{-1e30f, -1e30f}, {-1e30f, -1e30f}};
    float lrow[2][2] = {{0.f, 0.f}, {0.f, 0.f}};

    const float NEGINF = __int_as_float(0xff800000);

    for (int ch = 0; ch < nch; ch++) {
        const uint32_t kvb = (ch & 1) ? KV1 : KV0;
        if (ch + 1 < nch) {
            load_kv(c0 + (ch + 1) * 64, (ch & 1) ? KV0 : KV1);
            cp_wait1();
        } else {
            cp_wait0();
        }
        __syncthreads();

        const int c = c0 + ch * 64;

        float S[2][8][4];
#pragma unroll
        for (int mt = 0; mt < 2; mt++)
#pragma unroll
            for (int nt = 0; nt < 8; nt++)
#pragma unroll
                for (int r = 0; r < 4; r++) S[mt][nt][r] = 0.0f;

#pragma unroll
        for (int kt = 0; kt < 4; kt++) {
            uint32_t qa[2][4], qla[2][4];
#pragma unroll
            for (int mt = 0; mt < 2; mt++) {
                int row = wid * 32 + mt * 16 + (lane & 15);
                int kb  = kt * 32 + ((lane >> 4) << 4);
                uint32_t sw = swz128((uint32_t)(row * 128 + kb));
                ldmatrix_x4(qa[mt][0], qa[mt][1], qa[mt][2], qa[mt][3], QHs + sw);
                ldmatrix_x4(qla[mt][0], qla[mt][1], qla[mt][2], qla[mt][3], QLs + sw);
            }
#pragma unroll
            for (int np = 0; np < 4; np++) {
                int nr = np * 16 + ((lane >> 4) & 1) * 8 + (lane & 7);
                int kb = kt * 32 + ((lane >> 3) & 1) * 16;
                uint32_t sw = swz128((uint32_t)(nr * 128 + kb));
                uint32_t kf[4], klf[4];
                ldmatrix_x4(kf[0], kf[1], kf[2], kf[3], kvb + 0 + sw);
                ldmatrix_x4(klf[0], klf[1], klf[2], klf[3], kvb + 8192 + sw);
#pragma unroll
                for (int mt = 0; mt < 2; mt++)
#pragma unroll
                    for (int half = 0; half < 2; half++) {
                        int nt = np * 2 + half;
                        mma16816(S[mt][nt], qa[mt],  kf[half * 2],  kf[half * 2 + 1]);
                        mma16816(S[mt][nt], qa[mt],  klf[half * 2], klf[half * 2 + 1]);
                        mma16816(S[mt][nt], qla[mt], kf[half * 2],  kf[half * 2 + 1]);
                    }
            }
        }

        uint32_t Phi[2][4][4], Plo[2][4][4];
#pragma unroll
        for (int mt = 0; mt < 2; mt++) {
            int i0 = q0 + wid * 32 + mt * 16 + (lane >> 2);
            int i1 = i0 + 8;
#pragma unroll
            for (int nt = 0; nt < 8; nt++) {
                int j = c + nt * 8 + (lane & 3) * 2;
                if (j     > i0 || j     < i0 - WINDOW) S[mt][nt][0] = NEGINF;
                if (j + 1 > i0 || j + 1 < i0 - WINDOW) S[mt][nt][1] = NEGINF;
                if (j     > i1 || j     < i1 - WINDOW) S[mt][nt][2] = NEGINF;
                if (j + 1 > i1 || j + 1 < i1 - WINDOW) S[mt][nt][3] = NEGINF;
            }
#pragma unroll
            for (int half = 0; half < 2; half++) {
                float cm = NEGINF;
#pragma unroll
                for (int nt = 0; nt < 8; nt++)
                    cm = fmaxf(cm, fmaxf(S[mt][nt][half * 2], S[mt][nt][half * 2 + 1]));
                cm = fmaxf(cm, __shfl_xor_sync(0xffffffffu, cm, 1));
                cm = fmaxf(cm, __shfl_xor_sync(0xffffffffu, cm, 2));
                float mold = mrow[mt][half];
                float mnew = fmaxf(mold, cm);
                float corr = __expf(mold - mnew);
                mrow[mt][half] = mnew;
                float psum = 0.0f;
#pragma unroll
                for (int nt = 0; nt < 8; nt++) {
                    float p0 = __expf(S[mt][nt][half * 2]     - mnew);
                    float p1 = __expf(S[mt][nt][half * 2 + 1] - mnew);
                    psum += p0 + p1;
                    O[mt][nt][half * 2]     *= corr;
                    O[mt][nt][half * 2 + 1] *= corr;
                    uint32_t hp = packbf(p0, p1);
                    float r0 = p0 - __bfloat162float(__ushort_as_bfloat16((uint16_t)(hp & 0xFFFF)));
                    float r1 = p1 - __bfloat162float(__ushort_as_bfloat16((uint16_t)(hp >> 16)));
                    int kt = nt >> 1, hh = nt & 1;
                    Phi[mt][kt][hh * 2 + half] = hp;
                    Plo[mt][kt][hh * 2 + half] = packbf(r0, r1);
                }
                psum += __shfl_xor_sync(0xffffffffu, psum, 1);
                psum += __shfl_xor_sync(0xffffffffu, psum, 2);
                lrow[mt][half] = lrow[mt][half] * corr + psum;
            }
        }

#pragma unroll
        for (int kt = 0; kt < 4; kt++) {
#pragma unroll
            for (int np = 0; np < 4; np++) {
                int g = lane >> 3;
                int key = kt * 16 + (g & 1) * 8 + (lane & 7);
                int nb  = np * 32 + ((g >> 1) << 4);
                uint32_t sw = swz128((uint32_t)(key * 128 + nb));
                uint32_t vf[4], vlf[4];
                ldmatrix_x4t(vf[0], vf[1], vf[2], vf[3], kvb + 16384 + sw);
                ldmatrix_x4t(vlf[0], vlf[1], vlf[2], vlf[3], kvb + 24576 + sw);
#pragma unroll
                for (int mt = 0; mt < 2; mt++)
#pragma unroll
                    for (int half = 0; half < 2; half++) {
                        int nt = np * 2 + half;
                        mma16816(O[mt][nt], Phi[mt][kt], vf[half * 2],  vf[half * 2 + 1]);
                        mma16816(O[mt][nt], Phi[mt][kt], vlf[half * 2], vlf[half * 2 + 1]);
                        mma16816(O[mt][nt], Plo[mt][kt], vf[half * 2],  vf[half * 2 + 1]);
                    }
            }
        }
        __syncthreads();
    }

#pragma unroll
    for (int mt = 0; mt < 2; mt++) {
        size_t rA = rowbase + wid * 32 + mt * 16 + (lane >> 2);
        size_t rB = rA + 8;
        float inv0 = 1.0f / lrow[mt][0];
        float inv1 = 1.0f / lrow[mt][1];
#pragma unroll
        for (int nt = 0; nt < 8; nt++) {
            int col = hoff + nt * 8 + (lane & 3) * 2;
            float o00 = O[mt][nt][0] * inv0, o01 = O[mt][nt][1] * inv0;
            float o10 = O[mt][nt][2] * inv1, o11 = O[mt][nt][3] * inv1;
            uint32_t hA = packbf(o00, o01);
            uint32_t hB = packbf(o10, o11);
            float a0 = o00 - __bfloat162float(__ushort_as_bfloat16((uint16_t)(hA & 0xFFFF)));
            float a1 = o01 - __bfloat162float(__ushort_as_bfloat16((uint16_t)(hA >> 16)));
            float b0 = o10 - __bfloat162float(__ushort_as_bfloat16((uint16_t)(hB & 0xFFFF)));
            float b1 = o11 - __bfloat162float(__ushort_as_bfloat16((uint16_t)(hB >> 16)));
            uint32_t lA = packbf(a0, a1);
            uint32_t lB = packbf(b0, b1);
            __nv_bfloat16* pA = acat + rA * KCAT + col;
            __nv_bfloat16* pB = acat + rB * KCAT + col;
            *reinterpret_cast<uint32_t*>(pA) = hA;
            *reinterpret_cast<uint32_t*>(pA + D_MODEL) = hA;
            *reinterpret_cast<uint32_t*>(pA + 2 * D_MODEL) = lA;
            *reinterpret_cast<uint32_t*>(pB) = hB;
            *reinterpret_cast<uint32_t*>(pB + D_MODEL) = hB;
            *reinterpret_cast<uint32_t*>(pB + 2 * D_MODEL) = lB;
        }
    }
}

// ---------------------------------------------------------------------------
// Launch.  Inputs: x, Wq, bq, Wk, bk, Wv, bv, Wo, bo
// ---------------------------------------------------------------------------
extern "C" void kernel_launch(void* const* d_in, const int* in_sizes, int n_in,
                              void* d_out, int out_size)
{
    const float* x  = (const float*)d_in[0];
    const float* Wq = (const float*)d_in[1];
    const float* bq = (const float*)d_in[2];
    const float* Wk = (const float*)d_in[3];
    const float* bk = (const float*)d_in[4];
    const float* Wv = (const float*)d_in[5];
    const float* bv = (const float*)d_in[6];
    const float* Wo = (const float*)d_in[7];
    const float* bo = (const float*)d_in[8];
    float* out = (float*)d_out;

    __nv_bfloat16 *acat, *bcat, *qh, *ql, *kh, *kl, *vh, *vl;
    cudaGetSymbolAddress((void**)&acat, g_acat);
    cudaGetSymbolAddress((void**)&bcat, g_bcat);
    cudaGetSymbolAddress((void**)&qh, g_qh);
    cudaGetSymbolAddress((void**)&ql, g_ql);
    cudaGetSymbolAddress((void**)&kh, g_kh);
    cudaGetSymbolAddress((void**)&kl, g_kl);
    cudaGetSymbolAddress((void**)&vh, g_vh);
    cudaGetSymbolAddress((void**)&vl, g_vl);

    cudaFuncSetAttribute(qkv_mma_kernel,
                         cudaFuncAttributeMaxDynamicSharedMemorySize, GEMM_SMEM_BYTES);
    cudaFuncSetAttribute(oproj_mma_kernel,
                         cudaFuncAttributeMaxDynamicSharedMemorySize, GEMM_SMEM_BYTES);
    cudaFuncSetAttribute(attn_tc_kernel,
                         cudaFuncAttributeMaxDynamicSharedMemorySize, ATT_SMEM);

    const size_t WSTRIDE = (size_t)D_MODEL * KCAT;

    convA_kernel<<<M_TOT * D_MODEL / 4 / 256, 256>>>(x, acat);
    dim3 cw_grid(32, 32, 4), cw_blk(32, 8);
    convW4_kernel<<<cw_grid, cw_blk>>>(Wq, Wk, Wv, Wo, bcat);

    // fused QKV projections -> split bf16 (Q pre-scaled by 0.125)
    dim3 qkv_grid(24, 32);
    qkv_mma_kernel<<<qkv_grid, 256, GEMM_SMEM_BYTES>>>(acat, bcat, bq, bk, bv,
                                                       qh, ql, kh, kl, vh, vl);

    // tensor-core windowed attention -> writes acat [hi|hi|lo] directly
    dim3 attn_grid(SEQ / 128, NHEADS, BATCH);    // (16, 16, 2)
    attn_tc_kernel<<<attn_grid, 128, ATT_SMEM>>>(qh, ql, kh, kl, vh, vl, acat);

    // output projection -> fp32
    dim3 o_grid(8, 32);
    oproj_mma_kernel<<<o_grid, 256, GEMM_SMEM_BYTES>>>(acat, bcat + 3 * WSTRIDE, bo, out);
}